// round 2
// baseline (speedup 1.0000x reference)
#include <cuda_runtime.h>
#include <math.h>

// Problem dims (fixed by the dataset)
#define N_ROWS 32768
#define LATENT 256
#define N_ANCH 4096
#define FDIM   768

// GEMM1 tiling
#define BM 128
#define BC 128
#define BK 16
#define TM 8
#define TN 8
// 256 threads: tx = tid%16 -> anchor cols (interleaved j*16+tx), ty = tid/16 -> z rows

// Scratch (device globals: allocation-free per harness rules)
__device__ float g_zsq[N_ROWS];
__device__ float g_asq[N_ANCH];

// Packed dual-FMA (sm_100+/sm_103a only; 2x FFMA throughput, PTX-only form)
__device__ __forceinline__ unsigned long long ffma2(unsigned long long a,
                                                    unsigned long long b,
                                                    unsigned long long c) {
    unsigned long long d;
    asm("fma.rn.f32x2 %0, %1, %2, %3;" : "=l"(d) : "l"(a), "l"(b), "l"(c));
    return d;
}

// ---------------------------------------------------------------------------
// Zero the output (out is poisoned to 0xAA by the harness).
// ---------------------------------------------------------------------------
__global__ void rkhs_zero_out(float4* __restrict__ out, int n4) {
    int i = blockIdx.x * blockDim.x + threadIdx.x;
    if (i < n4) out[i] = make_float4(0.f, 0.f, 0.f, 0.f);
}

// ---------------------------------------------------------------------------
// Squared norms of z rows and anchor rows. One warp per row (256 floats).
// ---------------------------------------------------------------------------
__global__ void rkhs_sqnorm(const float* __restrict__ z,
                            const float* __restrict__ anch) {
    int gw   = (blockIdx.x * blockDim.x + threadIdx.x) >> 5;
    int lane = threadIdx.x & 31;
    if (gw >= N_ROWS + N_ANCH) return;

    const float* src;
    float*       dst;
    if (gw < N_ROWS) { src = z    + (size_t)gw * LATENT;            dst = &g_zsq[gw]; }
    else             { src = anch + (size_t)(gw - N_ROWS) * LATENT; dst = &g_asq[gw - N_ROWS]; }

    const float4* p = (const float4*)src;
    float s = 0.f;
#pragma unroll
    for (int i = 0; i < LATENT / 4 / 32; i++) {
        float4 v = p[lane + i * 32];
        s += v.x * v.x + v.y * v.y + v.z * v.z + v.w * v.w;
    }
#pragma unroll
    for (int o = 16; o; o >>= 1) s += __shfl_xor_sync(0xffffffffu, s, o);
    if (lane == 0) *dst = s;
}

// ---------------------------------------------------------------------------
// Main fused kernel:
//   cross tile (128x128) = z_tile @ anchors_tile^T   (fp32, f32x2 packed FMA)
//   p = exp2( max(zsq + asq - 2*cross, 0) * (-0.5/(l^2+1e-7)) * log2(e) )
//   if any p != 0 in the CTA -> accumulate p @ alpha into out via atomicAdd
//   (out is pre-zeroed; in practice every p underflows to 0 and the CTA exits)
// ---------------------------------------------------------------------------
__global__ __launch_bounds__(256)
void rkhs_main(const float* __restrict__ z,
               const float* __restrict__ anch,
               const float* __restrict__ alpha,
               const float* __restrict__ logls,
               float* __restrict__ out) {
    __shared__ float Zs[BK][BM];        // z transposed tile:       Zs[k][row]
    __shared__ float As2[BK][2 * BC];   // anchors, each value DUPLICATED:
                                        //   As2[k][2c] = As2[k][2c+1] = a[c][k]

    const int m0  = blockIdx.y * BM;
    const int c0  = blockIdx.x * BC;
    const int tid = threadIdx.x;
    const int tx  = tid & 15;
    const int ty  = tid >> 4;

    // acc2[p][j]: packed pair of accumulators for rows (2p, 2p+1), column j*16+tx
    unsigned long long acc2[TM / 2][TN];
#pragma unroll
    for (int p = 0; p < TM / 2; p++)
#pragma unroll
        for (int j = 0; j < TN; j++) acc2[p][j] = 0ull;

    for (int k0 = 0; k0 < LATENT; k0 += BK) {
        // Load both tiles. 512 float4 jobs per input; job = row*4 + kquad.
        // A warp covers 8 rows x 16 contiguous k's (64B/row) -> coalesced LDG.
#pragma unroll
        for (int i = 0; i < 2; i++) {
            int job = tid + i * 256;          // 0..511
            int r   = job >> 2;
            int kq  = (job & 3) << 2;
            float4 v = *(const float4*)&z[(size_t)(m0 + r) * LATENT + k0 + kq];
            Zs[kq + 0][r] = v.x; Zs[kq + 1][r] = v.y;
            Zs[kq + 2][r] = v.z; Zs[kq + 3][r] = v.w;
            float4 w = *(const float4*)&anch[(size_t)(c0 + r) * LATENT + k0 + kq];
            *(float2*)&As2[kq + 0][2 * r] = make_float2(w.x, w.x);
            *(float2*)&As2[kq + 1][2 * r] = make_float2(w.y, w.y);
            *(float2*)&As2[kq + 2][2 * r] = make_float2(w.z, w.z);
            *(float2*)&As2[kq + 3][2 * r] = make_float2(w.w, w.w);
        }
        __syncthreads();

#pragma unroll
        for (int k = 0; k < BK; k++) {
            // z row-pairs: contiguous in Zs -> direct LDS.64 (broadcast across tx)
            unsigned long long zp[TM / 2];
#pragma unroll
            for (int p = 0; p < TM / 2; p++)
                zp[p] = *(const unsigned long long*)&Zs[k][ty * TM + 2 * p];
            // duplicated anchor values: direct LDS.64, stride 2 words across tx
            // (interleaved column mapping j*16+tx -> conflict-free)
            unsigned long long ad[TN];
#pragma unroll
            for (int j = 0; j < TN; j++)
                ad[j] = *(const unsigned long long*)&As2[k][2 * (j * 16 + tx)];
#pragma unroll
            for (int p = 0; p < TM / 2; p++)
#pragma unroll
                for (int j = 0; j < TN; j++)
                    acc2[p][j] = ffma2(zp[p], ad[j], acc2[p][j]);
        }
        __syncthreads();
    }

    // Unpack packed accumulators: acc[i][j], i = 2p + (lo/hi)
    float acc[TM][TN];
#pragma unroll
    for (int p = 0; p < TM / 2; p++)
#pragma unroll
        for (int j = 0; j < TN; j++) {
            unsigned int lo = (unsigned int)(acc2[p][j] & 0xffffffffull);
            unsigned int hi = (unsigned int)(acc2[p][j] >> 32);
            acc[2 * p + 0][j] = __uint_as_float(lo);
            acc[2 * p + 1][j] = __uint_as_float(hi);
        }

    // Epilogue: RBF kernel values (overwrite acc with p).
    const float lsv = logls[0];
    const float l   = expf(lsv);
    const float c2  = (-0.5f / (l * l + 1e-7f)) * 1.44269504088896340736f; // * log2(e)

    float zq[TM], aq[TN];
#pragma unroll
    for (int i = 0; i < TM; i++) zq[i] = g_zsq[m0 + ty * TM + i];
#pragma unroll
    for (int j = 0; j < TN; j++) aq[j] = g_asq[c0 + j * 16 + tx];

    int any_local = 0;
#pragma unroll
    for (int i = 0; i < TM; i++) {
#pragma unroll
        for (int j = 0; j < TN; j++) {
            float d = zq[i] + aq[j] - 2.f * acc[i][j];
            d = fmaxf(d, 0.f);
            float p = exp2f(d * c2);
            acc[i][j] = p;
            any_local |= (p != 0.f);
        }
    }

    // CTA-wide "any nonzero kernel value" test. In expectation this is false
    // for every CTA (fp32 exp underflow at dist^2 > ~208, which is an ~8.8-sigma
    // left-tail event for ||z-a||^2 ~ 2*chi2_256), so GEMM2 is skipped entirely.
    if (!__syncthreads_or(any_local)) return;

    // Rare exact path: accumulate p @ alpha into the (pre-zeroed) output.
    // Perf-irrelevant; correctness-exact.
#pragma unroll 1
    for (int i = 0; i < TM; i++) {
#pragma unroll 1
        for (int j = 0; j < TN; j++) {
            float p = acc[i][j];
            if (p != 0.f) {
                int r = m0 + ty * TM + i;
                int c = c0 + j * 16 + tx;
                const float* al = &alpha[(size_t)c * FDIM];
                float*       o  = &out[(size_t)r * FDIM];
                for (int f = 0; f < FDIM; f++)
                    atomicAdd(&o[f], p * al[f]);
            }
        }
    }
}

// ---------------------------------------------------------------------------
extern "C" void kernel_launch(void* const* d_in, const int* in_sizes, int n_in,
                              void* d_out, int out_size) {
    const float* z     = (const float*)d_in[0];
    const float* anch  = (const float*)d_in[1];
    const float* alpha = (const float*)d_in[2];
    const float* logls = (const float*)d_in[3];
    float*       out   = (float*)d_out;

    int n4 = out_size / 4; // out_size = 32768*768, divisible by 4
    rkhs_zero_out<<<(n4 + 255) / 256, 256>>>((float4*)d_out, n4);

    int nwarps  = N_ROWS + N_ANCH;           // one warp per row
    int nblocks = (nwarps * 32 + 255) / 256; // 4608
    rkhs_sqnorm<<<nblocks, 256>>>(z, anch);

    dim3 grid(N_ANCH / BC, N_ROWS / BM);     // (32, 256)
    rkhs_main<<<grid, 256>>>(z, anch, alpha, logls, out);
}

// round 5
// speedup vs baseline: 5.6708x; 5.6708x over previous
#include <cuda_runtime.h>
#include <cuda_bf16.h>
#include <math.h>
#include <stdint.h>

// Problem dims (fixed by the dataset)
#define N_ROWS 32768
#define LATENT 256
#define N_ANCH 4096
#define FDIM   768

#define BM 128
#define BN 128
#define THREADS 512

// Screening threshold (log2 domain). fp32 exp returns nonzero only for
// arg2 > ~-150 (last subnormal). Flag conservatively at -170; the bf16 dot
// error perturbs the scaled exponent by << 1 (true values sit near -369).
// Flagged pairs are recomputed exactly in fp32 from global memory, so
// correctness never depends on bf16 precision.
#define ETHR (-170.0f)

// SMEM row stride for tiles: 256 bf16 + 8 pad = 264 bf16 = 528 B.
// 528 % 16 == 0 (ldmatrix alignment); 528 % 128 == 16 -> successive rows
// shift one 16B bank-group => ldmatrix 8-row phases conflict-free.
#define RSTRIDE 264
#define RSTRIDE_B (RSTRIDE * 2)
#define TILE_BYTES (BM * RSTRIDE_B)        // 67584
#define SM_OFF_ZQ 0
#define SM_OFF_AQ 512
#define SM_OFF_A  1024
#define SM_OFF_B  (SM_OFF_A + TILE_BYTES)
#define SMEM_DYN  (SM_OFF_B + TILE_BYTES)  // 136192 < 228KB carveout

// Scratch (device globals: allocation-free per harness rules)
__device__ float         g_zsq[N_ROWS];
__device__ float         g_asq[N_ANCH];
__device__ __nv_bfloat16 g_zb[N_ROWS * LATENT];
__device__ __nv_bfloat16 g_ab[N_ANCH * LATENT];

__device__ __forceinline__ uint32_t smem_u32(const void* p) {
    uint32_t a;
    asm("{ .reg .u64 t; cvta.to.shared.u64 t, %1; cvt.u32.u64 %0, t; }"
        : "=r"(a) : "l"(p));
    return a;
}

__device__ __forceinline__ void ldsm_x4(uint32_t& r0, uint32_t& r1,
                                        uint32_t& r2, uint32_t& r3,
                                        uint32_t addr) {
    asm volatile("ldmatrix.sync.aligned.m8n8.x4.shared.b16 {%0,%1,%2,%3}, [%4];"
                 : "=r"(r0), "=r"(r1), "=r"(r2), "=r"(r3) : "r"(addr));
}

__device__ __forceinline__ void mma_16816(float& c0, float& c1, float& c2, float& c3,
                                          uint32_t a0, uint32_t a1, uint32_t a2, uint32_t a3,
                                          uint32_t b0, uint32_t b1) {
    asm volatile("mma.sync.aligned.m16n8k16.row.col.f32.bf16.bf16.f32 "
                 "{%0,%1,%2,%3}, {%4,%5,%6,%7}, {%8,%9}, {%0,%1,%2,%3};"
                 : "+f"(c0), "+f"(c1), "+f"(c2), "+f"(c3)
                 : "r"(a0), "r"(a1), "r"(a2), "r"(a3), "r"(b0), "r"(b1));
}

// ---------------------------------------------------------------------------
__global__ void rkhs_zero_out(float4* __restrict__ out, int n4) {
    int i = blockIdx.x * blockDim.x + threadIdx.x;
    if (i < n4) out[i] = make_float4(0.f, 0.f, 0.f, 0.f);
}

// ---------------------------------------------------------------------------
// Prepass: fp32 -> bf16 conversion + squared norms. One warp per row.
// ---------------------------------------------------------------------------
__global__ void rkhs_prep(const float* __restrict__ z,
                          const float* __restrict__ anch) {
    int gw   = (blockIdx.x * blockDim.x + threadIdx.x) >> 5;
    int lane = threadIdx.x & 31;
    if (gw >= N_ROWS + N_ANCH) return;

    const float*    src;
    __nv_bfloat162* dstb;
    float*          dsq;
    if (gw < N_ROWS) {
        src  = z + (size_t)gw * LATENT;
        dstb = (__nv_bfloat162*)(g_zb + (size_t)gw * LATENT);
        dsq  = &g_zsq[gw];
    } else {
        int r = gw - N_ROWS;
        src  = anch + (size_t)r * LATENT;
        dstb = (__nv_bfloat162*)(g_ab + (size_t)r * LATENT);
        dsq  = &g_asq[r];
    }

    const float4* p = (const float4*)src;
    float s = 0.f;
#pragma unroll
    for (int i = 0; i < 2; i++) {
        int j = lane + i * 32;
        float4 v = p[j];
        s += v.x * v.x + v.y * v.y + v.z * v.z + v.w * v.w;
        dstb[2 * j + 0] = __floats2bfloat162_rn(v.x, v.y);
        dstb[2 * j + 1] = __floats2bfloat162_rn(v.z, v.w);
    }
#pragma unroll
    for (int o = 16; o; o >>= 1) s += __shfl_xor_sync(0xffffffffu, s, o);
    if (lane == 0) *dsq = s;
}

// ---------------------------------------------------------------------------
// Main: bf16 mma.sync GEMM (128x128x256 per CTA) + screening epilogue.
// Warp grid 4(m) x 4(n); warp tile 32x32; full K=256 resident in SMEM.
// ---------------------------------------------------------------------------
__global__ __launch_bounds__(THREADS, 1)
void rkhs_main(const float* __restrict__ z,
               const float* __restrict__ anch,
               const float* __restrict__ alpha,
               const float* __restrict__ logls,
               float* __restrict__ out) {
    extern __shared__ char smem[];
    const uint32_t sb = smem_u32(smem);

    const int m0   = blockIdx.y * BM;
    const int c0   = blockIdx.x * BN;
    const int tid  = threadIdx.x;
    const int wid  = tid >> 5;
    const int lane = tid & 31;
    const int wm   = wid & 3;          // m-block (32 rows)
    const int wn   = wid >> 2;         // n-block (32 cols)

    // --- Fill tiles: 4096 16B-chunk jobs per tile; warp = one row (coalesced) ---
    const uint4* gA = (const uint4*)(g_zb + (size_t)m0 * LATENT);
    const uint4* gB = (const uint4*)(g_ab + (size_t)c0 * LATENT);
    char* pA = smem + SM_OFF_A;
    char* pB = smem + SM_OFF_B;
#pragma unroll
    for (int i = 0; i < 8; i++) {
        int job = tid + i * THREADS;       // 0..4095
        int r   = job >> 5;
        int cc  = job & 31;
        uint32_t off = (uint32_t)r * RSTRIDE_B + (uint32_t)cc * 16;
        *(uint4*)(pA + off) = gA[job];
        *(uint4*)(pB + off) = gB[job];
    }
    if (tid < 128)      ((float*)(smem + SM_OFF_ZQ))[tid]       = g_zsq[m0 + tid];
    else if (tid < 256) ((float*)(smem + SM_OFF_AQ))[tid - 128] = g_asq[c0 + tid - 128];
    __syncthreads();

    // --- MMA mainloop ---
    // A (x4): lanes 0-15 -> rows m+0..15 byte 0 (k0-7|k8-15 via reg order),
    //         lanes 16-31 -> same rows, byte 16. Canonical a0..a3 order.
    // B (x4): [n][k] tiles, non-trans; matrices = [n0-7,k0-7],[n0-7,k8-15],
    //         [n8-15,k0-7],[n8-15,k8-15]; n-tile 0 uses {r0,r1}, tile 1 {r2,r3}.
    const uint32_t aBase = sb + SM_OFF_A
        + (uint32_t)(wm * 32 + (lane & 15)) * RSTRIDE_B + (uint32_t)(lane >> 4) * 16;
    const uint32_t bBase = sb + SM_OFF_B
        + (uint32_t)(wn * 32 + ((lane >> 4) << 3) + (lane & 7)) * RSTRIDE_B
        + (uint32_t)((lane >> 3) & 1) * 16;

    float c[2][4][4];
#pragma unroll
    for (int mi = 0; mi < 2; mi++)
#pragma unroll
        for (int ni = 0; ni < 4; ni++)
#pragma unroll
            for (int q = 0; q < 4; q++) c[mi][ni][q] = 0.f;

#pragma unroll
    for (int kt = 0; kt < LATENT / 16; kt++) {
        const uint32_t ko = (uint32_t)kt * 32;   // 16 bf16 = 32B
        uint32_t a[2][4], b[2][4];
        ldsm_x4(a[0][0], a[0][1], a[0][2], a[0][3], aBase + ko);
        ldsm_x4(a[1][0], a[1][1], a[1][2], a[1][3], aBase + ko + 16u * RSTRIDE_B);
        ldsm_x4(b[0][0], b[0][1], b[0][2], b[0][3], bBase + ko);
        ldsm_x4(b[1][0], b[1][1], b[1][2], b[1][3], bBase + ko + 16u * RSTRIDE_B);
#pragma unroll
        for (int mi = 0; mi < 2; mi++)
#pragma unroll
            for (int ni = 0; ni < 4; ni++)
                mma_16816(c[mi][ni][0], c[mi][ni][1], c[mi][ni][2], c[mi][ni][3],
                          a[mi][0], a[mi][1], a[mi][2], a[mi][3],
                          b[ni >> 1][(ni & 1) * 2], b[ni >> 1][(ni & 1) * 2 + 1]);
    }

    // --- Screening epilogue (accumulator: row = lane>>2 (+8 for q>=2),
    //     col = 2*(lane&3) (+1 for odd q)) ---
    const float lsv = logls[0];
    const float l   = expf(lsv);
    const float il2 = 1.0f / (l * l + 1e-7f);
    const float c2f = -0.5f * 1.44269504088896340736f * il2;

    const float* sZq = (const float*)(smem + SM_OFF_ZQ);
    const float* sAq = (const float*)(smem + SM_OFF_AQ);
    const int rBase = wm * 32 + (lane >> 2);
    const int nBase = wn * 32 + 2 * (lane & 3);

    int any_local = 0;
#pragma unroll
    for (int mi = 0; mi < 2; mi++) {
        float zq0 = sZq[rBase + mi * 16];
        float zq1 = sZq[rBase + mi * 16 + 8];
#pragma unroll
        for (int ni = 0; ni < 4; ni++) {
            float aq0 = sAq[nBase + ni * 8];
            float aq1 = sAq[nBase + ni * 8 + 1];
            float e0 = c2f * (zq0 + aq0 - 2.f * c[mi][ni][0]);
            float e1 = c2f * (zq0 + aq1 - 2.f * c[mi][ni][1]);
            float e2 = c2f * (zq1 + aq0 - 2.f * c[mi][ni][2]);
            float e3 = c2f * (zq1 + aq1 - 2.f * c[mi][ni][3]);
            any_local |= (e0 > ETHR) | (e1 > ETHR) | (e2 > ETHR) | (e3 > ETHR);
        }
    }

    // Expected: never flags (dist^2 ~ 512 >> cutoff ~207) -> CTA done.
    if (!__syncthreads_or(any_local)) return;

    // Exact fallback: recompute flagged pairs in fp32 from global memory.
#pragma unroll 1
    for (int mi = 0; mi < 2; mi++) {
#pragma unroll 1
        for (int ni = 0; ni < 4; ni++) {
#pragma unroll 1
            for (int q = 0; q < 4; q++) {
                int rl = rBase + mi * 16 + (q >> 1) * 8;
                int nl = nBase + ni * 8 + (q & 1);
                float e = c2f * (sZq[rl] + sAq[nl] - 2.f * c[mi][ni][q]);
                if (e > ETHR) {
                    int gr = m0 + rl;
                    int gc = c0 + nl;
                    const float* zr = z    + (size_t)gr * LATENT;
                    const float* ar = anch + (size_t)gc * LATENT;
                    float dot = 0.f, zq = 0.f, aq = 0.f;
                    for (int k = 0; k < LATENT; k++) {
                        dot = fmaf(zr[k], ar[k], dot);
                        zq  = fmaf(zr[k], zr[k], zq);
                        aq  = fmaf(ar[k], ar[k], aq);
                    }
                    float de = fmaxf(zq + aq - 2.f * dot, 0.f);
                    float p  = expf(-0.5f * de * il2);
                    if (p != 0.f) {
                        const float* al = alpha + (size_t)gc * FDIM;
                        float*       o  = out   + (size_t)gr * FDIM;
                        for (int f = 0; f < FDIM; f++) atomicAdd(&o[f], p * al[f]);
                    }
                }
            }
        }
    }
}

// ---------------------------------------------------------------------------
extern "C" void kernel_launch(void* const* d_in, const int* in_sizes, int n_in,
                              void* d_out, int out_size) {
    const float* z     = (const float*)d_in[0];
    const float* anch  = (const float*)d_in[1];
    const float* alpha = (const float*)d_in[2];
    const float* logls = (const float*)d_in[3];
    float*       out   = (float*)d_out;

    // Host-side driver attribute (idempotent, capture-legal, no allocation).
    cudaFuncSetAttribute(rkhs_main,
                         cudaFuncAttributeMaxDynamicSharedMemorySize, SMEM_DYN);

    int n4 = out_size / 4;
    rkhs_zero_out<<<(n4 + 255) / 256, 256>>>((float4*)d_out, n4);

    int nwarps  = N_ROWS + N_ANCH;
    int nblocks = (nwarps * 32 + 255) / 256;
    rkhs_prep<<<nblocks, 256>>>(z, anch);

    dim3 grid(N_ANCH / BN, N_ROWS / BM);     // (32, 256)
    rkhs_main<<<grid, THREADS, SMEM_DYN>>>(z, anch, alpha, logls, out);
}

// round 8
// speedup vs baseline: 6.6428x; 1.1714x over previous
#include <cuda_runtime.h>
#include <cuda_bf16.h>
#include <math.h>
#include <stdint.h>

// Problem dims (fixed by the dataset)
#define N_ROWS 32768
#define LATENT 256
#define N_ANCH 4096
#define FDIM   768

#define BM 128
#define BN 128
#define BK 64
#define NCHUNK (LATENT / BK)       // 4
#define THREADS 512

// Screening threshold (log2 domain). fp32 exp is nonzero only for arg2 >
// ~-150. Flag at -170 (conservative); flagged pairs get exact fp32 recompute,
// so correctness never depends on bf16 precision.
#define ETHR (-170.0f)

// SMEM: stage row stride 72 bf16 = 144 B (16B-aligned; rows shift one 16B
// bank-group -> ldmatrix 8-row phases and STS.128 phases conflict-free).
#define RSTRIDE_B   144
#define ATILE_B     (BM * RSTRIDE_B)           // 18432
#define STAGE_B     (2 * ATILE_B)              // 36864 (A then B)
#define SM_OFF_ZQ   0
#define SM_OFF_AQ   512
#define SM_OFF_ST   1024
#define SMEM_DYN    (SM_OFF_ST + 2 * STAGE_B)  // 74752 -> occ=2

// Scratch (device globals: allocation-free per harness rules)
__device__ float         g_zsq[N_ROWS];
__device__ float         g_asq[N_ANCH];
__device__ __nv_bfloat16 g_zb[N_ROWS * LATENT];
__device__ __nv_bfloat16 g_ab[N_ANCH * LATENT];

__device__ __forceinline__ uint32_t smem_u32(const void* p) {
    uint32_t a;
    asm("{ .reg .u64 t; cvta.to.shared.u64 t, %1; cvt.u32.u64 %0, t; }"
        : "=r"(a) : "l"(p));
    return a;
}
__device__ __forceinline__ void cp_async16(uint32_t dst, const void* src) {
    asm volatile("cp.async.cg.shared.global [%0], [%1], 16;"
                 :: "r"(dst), "l"(src));
}
#define CP_COMMIT() asm volatile("cp.async.commit_group;" ::: "memory")
#define CP_WAIT1()  asm volatile("cp.async.wait_group 1;" ::: "memory")
#define CP_WAIT0()  asm volatile("cp.async.wait_group 0;" ::: "memory")

__device__ __forceinline__ void ldsm_x4(uint32_t& r0, uint32_t& r1,
                                        uint32_t& r2, uint32_t& r3,
                                        uint32_t addr) {
    asm volatile("ldmatrix.sync.aligned.m8n8.x4.shared.b16 {%0,%1,%2,%3}, [%4];"
                 : "=r"(r0), "=r"(r1), "=r"(r2), "=r"(r3) : "r"(addr));
}
__device__ __forceinline__ void mma_16816(float& c0, float& c1, float& c2, float& c3,
                                          uint32_t a0, uint32_t a1, uint32_t a2, uint32_t a3,
                                          uint32_t b0, uint32_t b1) {
    asm volatile("mma.sync.aligned.m16n8k16.row.col.f32.bf16.bf16.f32 "
                 "{%0,%1,%2,%3}, {%4,%5,%6,%7}, {%8,%9}, {%0,%1,%2,%3};"
                 : "+f"(c0), "+f"(c1), "+f"(c2), "+f"(c3)
                 : "r"(a0), "r"(a1), "r"(a2), "r"(a3), "r"(b0), "r"(b1));
}

// ---------------------------------------------------------------------------
__global__ void rkhs_zero_out(float4* __restrict__ out, int n4) {
    int i = blockIdx.x * blockDim.x + threadIdx.x;
    if (i < n4) out[i] = make_float4(0.f, 0.f, 0.f, 0.f);
}

// ---------------------------------------------------------------------------
// Prepass: fp32 -> bf16 + squared norms. One warp per row.
// ---------------------------------------------------------------------------
__global__ void rkhs_prep(const float* __restrict__ z,
                          const float* __restrict__ anch) {
    int gw   = (blockIdx.x * blockDim.x + threadIdx.x) >> 5;
    int lane = threadIdx.x & 31;
    if (gw >= N_ROWS + N_ANCH) return;

    const float*    src;
    __nv_bfloat162* dstb;
    float*          dsq;
    if (gw < N_ROWS) {
        src  = z + (size_t)gw * LATENT;
        dstb = (__nv_bfloat162*)(g_zb + (size_t)gw * LATENT);
        dsq  = &g_zsq[gw];
    } else {
        int r = gw - N_ROWS;
        src  = anch + (size_t)r * LATENT;
        dstb = (__nv_bfloat162*)(g_ab + (size_t)r * LATENT);
        dsq  = &g_asq[r];
    }

    const float4* p = (const float4*)src;
    float s = 0.f;
#pragma unroll
    for (int i = 0; i < 2; i++) {
        int j = lane + i * 32;
        float4 v = p[j];
        s += v.x * v.x + v.y * v.y + v.z * v.z + v.w * v.w;
        dstb[2 * j + 0] = __floats2bfloat162_rn(v.x, v.y);
        dstb[2 * j + 1] = __floats2bfloat162_rn(v.z, v.w);
    }
#pragma unroll
    for (int o = 16; o; o >>= 1) s += __shfl_xor_sync(0xffffffffu, s, o);
    if (lane == 0) *dsq = s;
}

// ---------------------------------------------------------------------------
// Issue cp.async loads for k-chunk c into stage s. 2048 16B jobs
// (1024 A + 1024 B); 4 per thread. Gmem row = 512 B; chunk = 128 B.
// ---------------------------------------------------------------------------
__device__ __forceinline__ void load_stage(char* smem, int s, int c,
                                           const char* gA, const char* gB,
                                           int tid) {
    char* stA = smem + SM_OFF_ST + s * STAGE_B;
    char* stB = stA + ATILE_B;
    const uint32_t cb = (uint32_t)c * (BK * 2);   // 128 B gmem chunk offset
#pragma unroll
    for (int i = 0; i < 4; i++) {
        int job = tid + i * THREADS;              // 0..2047
        int jj  = job & 1023;
        int r   = jj >> 3;
        int cc  = jj & 7;
        uint32_t soff = (uint32_t)r * RSTRIDE_B + (uint32_t)cc * 16;
        size_t   goff = (size_t)r * (LATENT * 2) + cb + (uint32_t)cc * 16;
        if (job < 1024) cp_async16(smem_u32(stA + soff), gA + goff);
        else            cp_async16(smem_u32(stB + soff), gB + goff);
    }
}

// ---------------------------------------------------------------------------
// Main: bf16 mma.sync GEMM (128x128x256 per CTA), cp.async double-buffered
// over 4 K-chunks of 64, + screening epilogue. Warp grid 4x4, tile 32x32.
// ---------------------------------------------------------------------------
__global__ __launch_bounds__(THREADS, 2)
void rkhs_main(const float* __restrict__ z,
               const float* __restrict__ anch,
               const float* __restrict__ alpha,
               const float* __restrict__ logls,
               float* __restrict__ out) {
    extern __shared__ char smem[];
    const uint32_t sb = smem_u32(smem);

    const int m0   = blockIdx.y * BM;
    const int c0   = blockIdx.x * BN;
    const int tid  = threadIdx.x;
    const int wid  = tid >> 5;
    const int lane = tid & 31;
    const int wm   = wid & 3;
    const int wn   = wid >> 2;

    const char* gA = (const char*)(g_zb + (size_t)m0 * LATENT);
    const char* gB = (const char*)(g_ab + (size_t)c0 * LATENT);

    // Stage norms first (plain LDG/STS: latency overlaps prologue cp.asyncs).
    if (tid < 128)      ((float*)(smem + SM_OFF_ZQ))[tid]       = g_zsq[m0 + tid];
    else if (tid < 256) ((float*)(smem + SM_OFF_AQ))[tid - 128] = g_asq[c0 + tid - 128];

    // Prologue: stage 0 <- chunk 0, stage 1 <- chunk 1.
    load_stage(smem, 0, 0, gA, gB, tid);
    CP_COMMIT();
    load_stage(smem, 1, 1, gA, gB, tid);
    CP_COMMIT();

    // Fragment base offsets within a stage (A then B), RSTRIDE_B=144.
    const uint32_t aOff = (uint32_t)(wm * 32 + (lane & 15)) * RSTRIDE_B
                        + (uint32_t)(lane >> 4) * 16;
    const uint32_t bOff = (uint32_t)(wn * 32 + ((lane >> 4) << 3) + (lane & 7)) * RSTRIDE_B
                        + (uint32_t)((lane >> 3) & 1) * 16;

    float c[2][4][4];
#pragma unroll
    for (int mi = 0; mi < 2; mi++)
#pragma unroll
        for (int ni = 0; ni < 4; ni++)
#pragma unroll
            for (int q = 0; q < 4; q++) c[mi][ni][q] = 0.f;

#pragma unroll
    for (int ch = 0; ch < NCHUNK; ch++) {
        if (ch < NCHUNK - 1) CP_WAIT1(); else CP_WAIT0();
        __syncthreads();

        const uint32_t stA = sb + SM_OFF_ST + (uint32_t)(ch & 1) * STAGE_B;
        const uint32_t stB = stA + ATILE_B;
        const uint32_t aB  = stA + aOff;
        const uint32_t bB  = stB + bOff;

#pragma unroll
        for (int kt = 0; kt < BK / 16; kt++) {
            const uint32_t ko = (uint32_t)kt * 32;
            uint32_t a[2][4], b[2][4];
            ldsm_x4(a[0][0], a[0][1], a[0][2], a[0][3], aB + ko);
            ldsm_x4(a[1][0], a[1][1], a[1][2], a[1][3], aB + ko + 16u * RSTRIDE_B);
            ldsm_x4(b[0][0], b[0][1], b[0][2], b[0][3], bB + ko);
            ldsm_x4(b[1][0], b[1][1], b[1][2], b[1][3], bB + ko + 16u * RSTRIDE_B);
#pragma unroll
            for (int mi = 0; mi < 2; mi++)
#pragma unroll
                for (int ni = 0; ni < 4; ni++)
                    mma_16816(c[mi][ni][0], c[mi][ni][1], c[mi][ni][2], c[mi][ni][3],
                              a[mi][0], a[mi][1], a[mi][2], a[mi][3],
                              b[ni >> 1][(ni & 1) * 2], b[ni >> 1][(ni & 1) * 2 + 1]);
        }

        if (ch + 2 < NCHUNK) {
            __syncthreads();   // all warps done reading this stage
            load_stage(smem, ch & 1, ch + 2, gA, gB, tid);
            CP_COMMIT();
        }
    }

    // --- Screening epilogue (acc: row = lane>>2 (+8 q>=2), col = 2*(lane&3) (+1 odd q)) ---
    const float lsv = logls[0];
    const float l   = expf(lsv);
    const float il2 = 1.0f / (l * l + 1e-7f);
    const float c2f = -0.5f * 1.44269504088896340736f * il2;

    const float* sZq = (const float*)(smem + SM_OFF_ZQ);
    const float* sAq = (const float*)(smem + SM_OFF_AQ);
    const int rBase = wm * 32 + (lane >> 2);
    const int nBase = wn * 32 + 2 * (lane & 3);

    int any_local = 0;
#pragma unroll
    for (int mi = 0; mi < 2; mi++) {
        float zq0 = sZq[rBase + mi * 16];
        float zq1 = sZq[rBase + mi * 16 + 8];
#pragma unroll
        for (int ni = 0; ni < 4; ni++) {
            float aq0 = sAq[nBase + ni * 8];
            float aq1 = sAq[nBase + ni * 8 + 1];
            float e0 = c2f * (zq0 + aq0 - 2.f * c[mi][ni][0]);
            float e1 = c2f * (zq0 + aq1 - 2.f * c[mi][ni][1]);
            float e2 = c2f * (zq1 + aq0 - 2.f * c[mi][ni][2]);
            float e3 = c2f * (zq1 + aq1 - 2.f * c[mi][ni][3]);
            any_local |= (e0 > ETHR) | (e1 > ETHR) | (e2 > ETHR) | (e3 > ETHR);
        }
    }

    // Expected: never flags (dist^2 ~ 512 >> cutoff ~207) -> CTA done.
    if (!__syncthreads_or(any_local)) return;

    // Exact fp32 fallback for flagged pairs (cold; correctness-exact).
#pragma unroll 1
    for (int mi = 0; mi < 2; mi++) {
#pragma unroll 1
        for (int ni = 0; ni < 4; ni++) {
#pragma unroll 1
            for (int q = 0; q < 4; q++) {
                int rl = rBase + mi * 16 + (q >> 1) * 8;
                int nl = nBase + ni * 8 + (q & 1);
                float e = c2f * (sZq[rl] + sAq[nl] - 2.f * c[mi][ni][q]);
                if (e > ETHR) {
                    int gr = m0 + rl;
                    int gc = c0 + nl;
                    const float* zr = z    + (size_t)gr * LATENT;
                    const float* ar = anch + (size_t)gc * LATENT;
                    float dot = 0.f, zq = 0.f, aq = 0.f;
                    for (int k = 0; k < LATENT; k++) {
                        dot = fmaf(zr[k], ar[k], dot);
                        zq  = fmaf(zr[k], zr[k], zq);
                        aq  = fmaf(ar[k], ar[k], aq);
                    }
                    float de = fmaxf(zq + aq - 2.f * dot, 0.f);
                    float p  = expf(-0.5f * de * il2);
                    if (p != 0.f) {
                        const float* al = alpha + (size_t)gc * FDIM;
                        float*       o  = out   + (size_t)gr * FDIM;
                        for (int f = 0; f < FDIM; f++) atomicAdd(&o[f], p * al[f]);
                    }
                }
            }
        }
    }
}

// ---------------------------------------------------------------------------
extern "C" void kernel_launch(void* const* d_in, const int* in_sizes, int n_in,
                              void* d_out, int out_size) {
    const float* z     = (const float*)d_in[0];
    const float* anch  = (const float*)d_in[1];
    const float* alpha = (const float*)d_in[2];
    const float* logls = (const float*)d_in[3];
    float*       out   = (float*)d_out;

    cudaFuncSetAttribute(rkhs_main,
                         cudaFuncAttributeMaxDynamicSharedMemorySize, SMEM_DYN);

    int n4 = out_size / 4;
    rkhs_zero_out<<<(n4 + 255) / 256, 256>>>((float4*)d_out, n4);

    int nwarps  = N_ROWS + N_ANCH;
    int nblocks = (nwarps * 32 + 255) / 256;
    rkhs_prep<<<nblocks, 256>>>(z, anch);

    dim3 grid(N_ANCH / BN, N_ROWS / BM);     // (32, 256)
    rkhs_main<<<grid, THREADS, SMEM_DYN>>>(z, anch, alpha, logls, out);
}